// round 15
// baseline (speedup 1.0000x reference)
#include <cuda_runtime.h>
#include <cuda_fp16.h>
#include <math.h>
#include <stdint.h>

#define DIMD 768
#define NTOK 1024
#define NB   16
#define MTOT (NB*NTOK)   // 16384

// ---------------- scratch (static device globals) --------------------------
__device__ float g_avg[NB*DIMD];
__device__ float g_pav[1024*DIMD];         // per-16-token-block column partials
__device__ float g_sq [MTOT];
__device__ float g_m  [MTOT];
__device__ float g_s1 [DIMD];              // colsum of fp16(w1 bottom half)
__device__ __half g_cat[MTOT*2*DIMD];      // [A | x] P16-format, K=1536
__device__ __half g_Ab [MTOT*DIMD];        // A B16-format (gram j-side)
__device__ __half g_m1p[MTOT*DIMD];        // m1 P16 (also gating source)
__device__ __half g_tp [MTOT*DIMD];        // t  P16
__device__ __half g_xlp[MTOT*DIMD];        // x*l3 P16
__device__ __half g_wB [5*DIMD*DIMD];      // weights B16 (w1 uses 2 blocks)
#define W1B 0
#define W2B (2*DIMD*DIMD)
#define W3B (3*DIMD*DIMD)
#define W4B (4*DIMD*DIMD)

// ---------------- helpers ---------------------------------------------------
__device__ __forceinline__ float gelu_exact(float v){ return v * normcdff(v); }
__device__ __forceinline__ uint32_t h2(float lo, float hi){
    __half2 h = __floats2half2_rn(lo, hi);
    return *(uint32_t*)&h;
}
__device__ __forceinline__ float h1r(float x){
    return __half2float(__float2half_rn(x));
}
__device__ __forceinline__ uint32_t smem_u32(const void* p){
    uint32_t a; asm("{ .reg .u64 t; cvta.to.shared.u64 t, %1; cvt.u32.u64 %0, t; }" : "=r"(a) : "l"(p));
    return a;
}
__device__ __forceinline__ void cpa16(uint32_t dst, const void* src){
    asm volatile("cp.async.cg.shared.global [%0], [%1], 16;" :: "r"(dst), "l"(src));
}
__device__ __forceinline__ void cpa_commit(){ asm volatile("cp.async.commit_group;"); }
__device__ __forceinline__ void cpa_wait1(){ asm volatile("cp.async.wait_group 1;"); }

__device__ __forceinline__ void mma16(float* cc, const uint32_t* a, const uint32_t* b){
    asm volatile("mma.sync.aligned.m16n8k16.row.col.f32.f16.f16.f32 "
       "{%0,%1,%2,%3},{%4,%5,%6,%7},{%8,%9},{%0,%1,%2,%3};"
       : "+f"(cc[0]),"+f"(cc[1]),"+f"(cc[2]),"+f"(cc[3])
       : "r"(a[0]),"r"(a[1]),"r"(a[2]),"r"(a[3]),"r"(b[0]),"r"(b[1]));
}

// smem: 3 stages x (A 8KB + B 8KB) = 48KB  (BK = 32)
#define STG 8192u
#define SBOFF 24576u
#define DSMEM_SZ 49152
#define LN_SMEM (16*772*4)

// ---------------------------------------------------------------- k_w1tr
// w1 [1536][768] -> B16 (K=1536)
__global__ void k_w1tr(const float* __restrict__ w1){
    size_t wd = (size_t)blockIdx.x*256 + threadIdx.x;   // 294912 uint2 words
    int sub = (int)(wd>>5), lane = (int)(wd&31);
    int n = (sub/96)*8 + (lane>>2);
    int kk = (sub%96)*16 + (lane&3)*2;
    uint2 o;
    o.x = h2(w1[(size_t)kk*DIMD+n],     w1[(size_t)(kk+1)*DIMD+n]);
    o.y = h2(w1[(size_t)(kk+8)*DIMD+n], w1[(size_t)(kk+9)*DIMD+n]);
    *(uint2*)(g_wB + W1B + wd*4) = o;
}

// ---------------------------------------------------------------- k_s1
// s1[n] = sum_{k=768..1535} fp16(w1[k][n])
__global__ void k_s1(const float* __restrict__ w1){
    int n = blockIdx.x*256 + threadIdx.x;
    float s = 0.f;
    #pragma unroll 8
    for (int k=DIMD; k<2*DIMD; k++) s += h1r(w1[(size_t)k*DIMD + n]);
    g_s1[n] = s;
}

// ---------------------------------------------------------------- k_avgx
// per 16-token block: column partial sums -> g_pav, fp16(x) -> cat upper P16
__global__ void __launch_bounds__(256) k_avgx(const float* __restrict__ x){
    extern __shared__ float s[];   // 16 x 772
    int tb = blockIdx.x;           // 0..1023
    int tid = threadIdx.x;
    #pragma unroll
    for (int it=0; it<12; it++){
        int idx = it*256 + tid;
        int row = idx/192, c4 = idx%192;
        int tok = tb*16 + row;
        float4 v = *(const float4*)(x + (size_t)tok*DIMD + c4*4);
        float* d = s + row*772 + c4*4;
        d[0]=v.x; d[1]=v.y; d[2]=v.z; d[3]=v.w;
    }
    __syncthreads();
    // P16 pack: fp16(x) into cat upper half (no m — factored to gemm1 epilogue)
    int w = tid>>5, l = tid&31;
    int rr = l>>2, c2 = (l&3)*2;
    #pragma unroll
    for (int it=0; it<6; it++){
        int ksub = it*8 + w;
        int kk = ksub*16 + c2;
        uint4 o;
        o.x = h2(s[rr*772+kk],       s[rr*772+kk+1]);
        o.y = h2(s[(rr+8)*772+kk],   s[(rr+8)*772+kk+1]);
        o.z = h2(s[rr*772+kk+8],     s[rr*772+kk+9]);
        o.w = h2(s[(rr+8)*772+kk+8], s[(rr+8)*772+kk+9]);
        *(uint4*)(g_cat + ((size_t)tb*96 + 48 + ksub)*256 + l*8) = o;
    }
    // column partial sums over 16 rows
    #pragma unroll
    for (int i=0;i<3;i++){
        int col = tid + 256*i;
        float ssum = 0.f;
        #pragma unroll
        for (int row=0; row<16; row++) ssum += s[row*772 + col];
        g_pav[(size_t)tb*DIMD + col] = ssum;
    }
}
__global__ void k_avg2(){
    int gid = blockIdx.x*256 + threadIdx.x;    // 0..12287
    int b = gid / DIMD, d = gid % DIMD;
    float ssum = 0.f;
    #pragma unroll
    for (int c=0;c<64;c++) ssum += g_pav[((size_t)(b*64+c))*DIMD + d];
    g_avg[gid] = ssum * (1.0f/NTOK);
}

// ---------------------------------------------------------------- k_ln  (R11 exact)
// A = fp16(avg*sigmoid(LN(x))) -> g_cat (P16 lower K) + g_Ab (B16)
__global__ void __launch_bounds__(256) k_ln(const float* __restrict__ x,
                                            const float* __restrict__ gamma,
                                            const float* __restrict__ beta){
    extern __shared__ float s[];               // 16 x 772
    int tb = blockIdx.x;
    int tid = threadIdx.x, w = tid>>5, l = tid&31;
    #pragma unroll
    for (int half=0; half<2; half++){
        int trow = w*2 + half;
        int tok  = tb*16 + trow;
        const float* xp = x + (size_t)tok*DIMD;
        float v[24]; float s1=0.f, s2=0.f;
        #pragma unroll
        for (int i=0;i<24;i++){ v[i]=xp[l+32*i]; s1+=v[i]; s2+=v[i]*v[i]; }
        #pragma unroll
        for (int o=16;o;o>>=1){ s1+=__shfl_xor_sync(~0u,s1,o); s2+=__shfl_xor_sync(~0u,s2,o); }
        float mu  = s1*(1.f/DIMD);
        float var = s2*(1.f/DIMD) - mu*mu;
        float rs  = rsqrtf(var + 1e-5f);
        const float* av = g_avg + (tok>>10)*DIMD;
        float asq = 0.f;
        #pragma unroll
        for (int i=0;i<24;i++){
            int d = l + 32*i;
            float y  = (v[i]-mu)*rs*gamma[d] + beta[d];
            float sg = 1.f/(1.f+expf(-y));
            float a  = h1r(av[d]*sg);
            s[trow*772 + d] = a;
            asq += a*a;
        }
        #pragma unroll
        for (int o=16;o;o>>=1) asq += __shfl_xor_sync(~0u,asq,o);
        if (l==0){ g_sq[tok]=asq; g_m[tok]=0.f; }
    }
    __syncthreads();
    int rr = l>>2, c2 = (l&3)*2;
    // P16 store (lower K half of g_cat)
    #pragma unroll
    for (int it=0; it<6; it++){
        int ksub = it*8 + w;                   // 0..47
        int kk = ksub*16 + c2;
        uint4 o;
        o.x = h2(s[rr*772+kk],       s[rr*772+kk+1]);
        o.y = h2(s[(rr+8)*772+kk],   s[(rr+8)*772+kk+1]);
        o.z = h2(s[rr*772+kk+8],     s[rr*772+kk+9]);
        o.w = h2(s[(rr+8)*772+kk+8], s[(rr+8)*772+kk+9]);
        *(uint4*)(g_cat + ((size_t)tb*96 + ksub)*256 + l*8) = o;
    }
    // B16 store: subtile=8 n x 16 k
    #pragma unroll
    for (int it=0; it<12; it++){
        int subidx = it*8 + w;                 // 0..95
        int nsub = subidx/48, ksub = subidx%48;
        int n = nsub*8 + rr;
        int kk = ksub*16 + c2;
        uint2 o;
        o.x = h2(s[n*772+kk],   s[n*772+kk+1]);
        o.y = h2(s[n*772+kk+8], s[n*772+kk+9]);
        *(uint2*)(g_Ab + (((size_t)(tb*2+nsub))*48 + ksub)*128 + l*4) = o;
    }
}

// ---------------------------------------------------------------- k_tr_rest
__global__ void k_tr_rest(const float* __restrict__ w2,
                          const float* __restrict__ w3,
                          const float* __restrict__ w4){
    int z = blockIdx.y;
    const float* wsrc = (z==0)? w2 : (z==1)? w3 : w4;
    __half* dst = g_wB + ((z==0)? W2B : (z==1)? W3B : W4B);
    size_t wd = (size_t)blockIdx.x*256 + threadIdx.x;
    int sub = (int)(wd>>5), lane = (int)(wd&31);
    int n = (sub/48)*8 + (lane>>2);
    int kk = (sub%48)*16 + (lane&3)*2;
    uint2 o;
    o.x = h2(wsrc[(size_t)kk*DIMD+n],     wsrc[(size_t)(kk+1)*DIMD+n]);
    o.y = h2(wsrc[(size_t)(kk+8)*DIMD+n], wsrc[(size_t)(kk+9)*DIMD+n]);
    *(uint2*)(dst + wd*4) = o;
}

// ---------------------------------------------------------------- k_gemm (BK=32)
// EPI 0: gelu   1: gelu*x*m1(P16)   2: gelu*x   3: gelu(acc + b + m[row]*s1[col])
// OUT 1: Cp=P16   2: Cr=raw row
template<int EPI, int OUT>
__global__ void __launch_bounds__(256) k_gemm(
    const __half* __restrict__ pA, const __half* __restrict__ pB,
    const float* __restrict__ bias, const float* __restrict__ x,
    const __half* __restrict__ m1h, __half* __restrict__ Cp,
    float* __restrict__ Cr, int Ktot)
{
    extern __shared__ float dsm[];
    uint32_t sA = smem_u32(dsm);
    uint32_t sB = sA + SBOFF;
    int tid = threadIdx.x, lane = tid&31;
    int wm = (tid>>5)&1, wn = tid>>6;
    int r = lane>>2, c = lane&3;
    int nb = blockIdx.x, mb = blockIdx.y;
    const int KT  = Ktot/32;
    const int K16 = Ktot>>4;

    float acc[4][4][4];
    #pragma unroll
    for (int a=0;a<4;a++)
      #pragma unroll
      for (int b=0;b<4;b++)
        #pragma unroll
        for (int e=0;e<4;e++) acc[a][b][e]=0.f;

    auto load_stage = [&](int kt){
        int st = kt % 3;
        uint32_t dA = sA + st*STG;
        uint32_t dB = sB + st*STG;
        #pragma unroll
        for (int it=0; it<2; it++){
            int wd = it*256 + tid;             // 0..511
            int rowsub = wd>>6, remA = wd&63;
            cpa16(dA + wd*16, pA + ((size_t)(mb*8+rowsub)*K16 + kt*2)*256 + remA*8);
            int nsub = wd>>5,  remB = wd&31;
            cpa16(dB + wd*16, pB + ((size_t)(nb*16+nsub)*K16 + kt*2)*128 + remB*8);
        }
        cpa_commit();
    };

    load_stage(0); load_stage(1);
    for (int kt=0; kt<KT; kt++){
        cpa_wait1();
        __syncthreads();
        if (kt+2 < KT) load_stage(kt+2); else cpa_commit();
        int st = kt % 3;
        uint32_t bA = sA + st*STG;
        uint32_t bB = sB + st*STG;
        #pragma unroll
        for (int jj=0;jj<2;jj++){
            uint4 af[4]; uint2 bf[4];
            #pragma unroll
            for (int mt=0;mt<4;mt++){
                uint32_t a = bA + (((wm*4+mt)*2+jj)<<9) + (lane<<4);
                asm volatile("ld.shared.v4.b32 {%0,%1,%2,%3},[%4];"
                  : "=r"(af[mt].x),"=r"(af[mt].y),"=r"(af[mt].z),"=r"(af[mt].w) : "r"(a));
            }
            #pragma unroll
            for (int nt=0;nt<4;nt++){
                uint32_t a = bB + (((wn*4+nt)*2+jj)<<8) + (lane<<3);
                asm volatile("ld.shared.v2.b32 {%0,%1},[%2];"
                  : "=r"(bf[nt].x),"=r"(bf[nt].y) : "r"(a));
            }
            #pragma unroll
            for (int mt=0;mt<4;mt++)
                #pragma unroll
                for (int nt=0;nt<4;nt++)
                    mma16(acc[mt][nt], &af[mt].x, &bf[nt].x);
        }
    }

    // epilogue
    #pragma unroll
    for (int mt=0; mt<4; mt++){
        int rp = mb*128 + wm*64 + mt*16 + r;
        float val[4][4];
        uint4 mws[2];
        float mm0=0.f, mm8=0.f;
        if (EPI==1){
            #pragma unroll
            for (int ntp=0; ntp<2; ntp++)
                mws[ntp] = *(const uint4*)(m1h +
                    (((size_t)(mb*8+wm*4+mt))*48 + nb*8+wn*2+ntp)*256 + lane*8);
        }
        if (EPI==3){ mm0 = g_m[rp]; mm8 = g_m[rp+8]; }
        #pragma unroll
        for (int nt=0; nt<4; nt++){
            int cg = nb*128 + wn*32 + nt*8 + 2*c;
            float bb0 = __ldg(bias+cg), bb1 = __ldg(bias+cg+1);
            float a0, a1, a2, a3;
            if (EPI==3){
                float sx0 = g_s1[cg], sx1 = g_s1[cg+1];
                a0 = gelu_exact(acc[mt][nt][0] + bb0 + mm0*sx0);
                a1 = gelu_exact(acc[mt][nt][1] + bb1 + mm0*sx1);
                a2 = gelu_exact(acc[mt][nt][2] + bb0 + mm8*sx0);
                a3 = gelu_exact(acc[mt][nt][3] + bb1 + mm8*sx1);
            } else {
                a0 = gelu_exact(acc[mt][nt][0] + bb0);
                a1 = gelu_exact(acc[mt][nt][1] + bb1);
                a2 = gelu_exact(acc[mt][nt][2] + bb0);
                a3 = gelu_exact(acc[mt][nt][3] + bb1);
            }
            size_t i0 = (size_t)rp*DIMD + cg, i1 = (size_t)(rp+8)*DIMD + cg;
            if (EPI==1){
                uint32_t lo = (nt&1)? mws[nt>>1].z : mws[nt>>1].x;
                uint32_t hi = (nt&1)? mws[nt>>1].w : mws[nt>>1].y;
                float2 m0 = __half22float2(*(__half2*)&lo);
                float2 m1v= __half22float2(*(__half2*)&hi);
                float2 xa=*(const float2*)(x+i0),  xb=*(const float2*)(x+i1);
                a0*=xa.x*m0.x; a1*=xa.y*m0.y; a2*=xb.x*m1v.x; a3*=xb.y*m1v.y;
            } else if (EPI==2){
                float2 xa=*(const float2*)(x+i0), xb=*(const float2*)(x+i1);
                a0*=xa.x; a1*=xa.y; a2*=xb.x; a3*=xb.y;
            }
            if (OUT==2){
                *(float2*)(Cr+i0) = make_float2(a0,a1);
                *(float2*)(Cr+i1) = make_float2(a2,a3);
            }
            val[nt][0]=a0; val[nt][1]=a1; val[nt][2]=a2; val[nt][3]=a3;
        }
        if (OUT==1){
            #pragma unroll
            for (int ntp=0; ntp<2; ntp++){
                uint4 o;
                o.x = h2(val[2*ntp][0],   val[2*ntp][1]);
                o.y = h2(val[2*ntp][2],   val[2*ntp][3]);
                o.z = h2(val[2*ntp+1][0], val[2*ntp+1][1]);
                o.w = h2(val[2*ntp+1][2], val[2*ntp+1][3]);
                *(uint4*)(Cp + (((size_t)(mb*8+wm*4+mt))*48 + nb*8+wn*2+ntp)*256 + lane*8) = o;
            }
        }
    }
}

// ---------------------------------------------------------------- k_gram (BK=32, R11 exact)
__global__ void __launch_bounds__(256) k_gram(){
    extern __shared__ float dsm[];
    uint32_t sA = smem_u32(dsm);
    uint32_t sB = sA + SBOFF;
    __shared__ int   smax_i[128], smax_j[128];
    __shared__ float sqi_s[128], sqj_s[128];

    int tid = threadIdx.x, lane = tid&31;
    int wm = (tid>>5)&1, wn = tid>>6;
    int r = lane>>2, c = lane&3;
    int b = blockIdx.y;
    int tt = blockIdx.x, ib = 0;
    while (tt >= (8-ib)){ tt -= (8-ib); ib++; }
    int jb = ib + tt;

    if (tid<128){
        sqi_s[tid] = g_sq[b*NTOK + ib*128 + tid];
        sqj_s[tid] = g_sq[b*NTOK + jb*128 + tid];
        smax_i[tid]=0; smax_j[tid]=0;
    }

    float acc[4][4][4];
    #pragma unroll
    for (int a=0;a<4;a++)
      #pragma unroll
      for (int bb=0;bb<4;bb++)
        #pragma unroll
        for (int e=0;e<4;e++) acc[a][bb][e]=0.f;

    const int KT = DIMD/32;   // 24
    auto load_stage = [&](int kt){
        int st = kt % 3;
        uint32_t dA = sA + st*STG;
        uint32_t dB = sB + st*STG;
        #pragma unroll
        for (int it=0; it<2; it++){
            int wd = it*256 + tid;
            int rowsub = wd>>6, remA = wd&63;
            cpa16(dA + wd*16, g_cat + ((size_t)(b*64+ib*8+rowsub)*96 + kt*2)*256 + remA*8);
            int nsub = wd>>5,  remB = wd&31;
            cpa16(dB + wd*16, g_Ab + ((size_t)(b*128+jb*16+nsub)*48 + kt*2)*128 + remB*8);
        }
        cpa_commit();
    };

    load_stage(0); load_stage(1);
    for (int kt=0; kt<KT; kt++){
        cpa_wait1();
        __syncthreads();
        if (kt+2 < KT) load_stage(kt+2); else cpa_commit();
        int st = kt % 3;
        uint32_t bA = sA + st*STG;
        uint32_t bB = sB + st*STG;
        #pragma unroll
        for (int jj=0;jj<2;jj++){
            uint4 af[4]; uint2 bf[4];
            #pragma unroll
            for (int mt=0;mt<4;mt++){
                uint32_t a = bA + (((wm*4+mt)*2+jj)<<9) + (lane<<4);
                asm volatile("ld.shared.v4.b32 {%0,%1,%2,%3},[%4];"
                  : "=r"(af[mt].x),"=r"(af[mt].y),"=r"(af[mt].z),"=r"(af[mt].w) : "r"(a));
            }
            #pragma unroll
            for (int nt=0;nt<4;nt++){
                uint32_t a = bB + (((wn*4+nt)*2+jj)<<8) + (lane<<3);
                asm volatile("ld.shared.v2.b32 {%0,%1},[%2];"
                  : "=r"(bf[nt].x),"=r"(bf[nt].y) : "r"(a));
            }
            #pragma unroll
            for (int mt=0;mt<4;mt++)
                #pragma unroll
                for (int nt=0;nt<4;nt++)
                    mma16(acc[mt][nt], &af[mt].x, &bf[nt].x);
        }
    }

    float rmax[8], cmax[8];
    #pragma unroll
    for (int i=0;i<8;i++){ rmax[i]=0.f; cmax[i]=0.f; }
    #pragma unroll
    for (int mt=0; mt<4; mt++){
        #pragma unroll
        for (int i2=0; i2<2; i2++){
            int rl = wm*64 + mt*16 + r + i2*8;
            float si = sqi_s[rl];
            #pragma unroll
            for (int nt=0; nt<4; nt++){
                #pragma unroll
                for (int q=0; q<2; q++){
                    int cl = wn*32 + nt*8 + 2*c + q;
                    float d2 = si + sqj_s[cl] - 2.f*acc[mt][nt][i2*2+q];
                    float dd = sqrtf(fmaxf(d2, 1e-12f));
                    rmax[mt*2+i2] = fmaxf(rmax[mt*2+i2], dd);
                    cmax[nt*2+q]  = fmaxf(cmax[nt*2+q],  dd);
                }
            }
        }
    }
    #pragma unroll
    for (int mt=0; mt<4; mt++)
        #pragma unroll
        for (int i2=0; i2<2; i2++)
            atomicMax(&smax_i[wm*64+mt*16+r+i2*8], __float_as_int(rmax[mt*2+i2]));
    #pragma unroll
    for (int nt=0; nt<4; nt++)
        #pragma unroll
        for (int q=0; q<2; q++)
            atomicMax(&smax_j[wn*32+nt*8+2*c+q], __float_as_int(cmax[nt*2+q]));
    __syncthreads();
    if (tid<128){
        atomicMax((int*)&g_m[b*NTOK + ib*128 + tid], smax_i[tid]);
        atomicMax((int*)&g_m[b*NTOK + jb*128 + tid], smax_j[tid]);
    }
}

// ---------------------------------------------------------------- launch
extern "C" void kernel_launch(void* const* d_in, const int* in_sizes, int n_in,
                              void* d_out, int out_size) {
    const float* x     = (const float*)d_in[0];
    const float* gamma = (const float*)d_in[1];
    const float* beta  = (const float*)d_in[2];
    const float* w1 = (const float*)d_in[3];
    const float* b1 = (const float*)d_in[4];
    const float* w2 = (const float*)d_in[5];
    const float* b2 = (const float*)d_in[6];
    const float* w3 = (const float*)d_in[7];
    const float* b3 = (const float*)d_in[8];
    const float* w4 = (const float*)d_in[9];
    const float* b4 = (const float*)d_in[10];
    float* out = (float*)d_out;

    cudaFuncSetAttribute(k_gram,      cudaFuncAttributeMaxDynamicSharedMemorySize, DSMEM_SZ);
    cudaFuncSetAttribute(k_ln,        cudaFuncAttributeMaxDynamicSharedMemorySize, LN_SMEM);
    cudaFuncSetAttribute(k_avgx,      cudaFuncAttributeMaxDynamicSharedMemorySize, LN_SMEM);
    cudaFuncSetAttribute(k_gemm<3,1>, cudaFuncAttributeMaxDynamicSharedMemorySize, DSMEM_SZ);
    cudaFuncSetAttribute(k_gemm<1,1>, cudaFuncAttributeMaxDynamicSharedMemorySize, DSMEM_SZ);
    cudaFuncSetAttribute(k_gemm<2,1>, cudaFuncAttributeMaxDynamicSharedMemorySize, DSMEM_SZ);
    cudaFuncSetAttribute(k_gemm<0,2>, cudaFuncAttributeMaxDynamicSharedMemorySize, DSMEM_SZ);

    __half *wB, *cat, *m1p, *tp, *xlp;
    cudaGetSymbolAddress((void**)&wB,  g_wB);
    cudaGetSymbolAddress((void**)&cat, g_cat);
    cudaGetSymbolAddress((void**)&m1p, g_m1p);
    cudaGetSymbolAddress((void**)&tp,  g_tp);
    cudaGetSymbolAddress((void**)&xlp, g_xlp);

    k_w1tr<<<1152, 256>>>(w1);
    k_s1  <<<DIMD/256, 256>>>(w1);
    k_avgx<<<MTOT/16, 256, LN_SMEM>>>(x);
    k_avg2<<<NB*DIMD/256, 256>>>();
    k_ln  <<<MTOT/16, 256, LN_SMEM>>>(x, gamma, beta);
    k_gram<<<dim3(36, NB), 256, DSMEM_SZ>>>();

    dim3 gg(DIMD/128, MTOT/128);
    // layer1: m1 = gelu([A|x] @ w1 + b1 + m*s1)   -> m1p (P16)
    k_gemm<3,1><<<gg,256,DSMEM_SZ>>>(cat, wB+W1B, b1, x, nullptr, m1p, nullptr, 2*DIMD);
    k_tr_rest<<<dim3(576, 3), 256>>>(w2, w3, w4);
    // layer2: t = x*m1*gelu(m1 @ w2 + b2)         -> tp (P16); m1 gating from m1p
    k_gemm<1,1><<<gg,256,DSMEM_SZ>>>(m1p, wB+W2B, b2, x, m1p,    tp,  nullptr, DIMD);
    // layer3: x*l3 = x*gelu(t @ w3 + b3)          -> xlp (P16)
    k_gemm<2,1><<<gg,256,DSMEM_SZ>>>(tp,  wB+W3B, b3, x, nullptr, xlp, nullptr, DIMD);
    // layer4: out = gelu((x*l3) @ w4 + b4)        -> out (row fp32)
    k_gemm<0,2><<<gg,256,DSMEM_SZ>>>(xlp, wB+W4B, b4, x, nullptr, nullptr, out, DIMD);
}

// round 16
// speedup vs baseline: 1.0407x; 1.0407x over previous
#include <cuda_runtime.h>
#include <cuda_fp16.h>
#include <math.h>
#include <stdint.h>

#define DIMD 768
#define NTOK 1024
#define NB   16
#define MTOT (NB*NTOK)   // 16384

// ---------------- scratch (static device globals) --------------------------
__device__ float g_avg[NB*DIMD];
__device__ float g_pav[8*NB*DIMD];
__device__ float g_sq [MTOT];
__device__ float g_m  [MTOT];
__device__ __half g_cat[MTOT*2*DIMD];      // [A | x+m] P16-format, K=1536
__device__ __half g_Ab [MTOT*DIMD];        // A B16-format (gram j-side)
__device__ __half g_m1p[MTOT*DIMD];        // m1 P16 (also gating source)
__device__ __half g_tp [MTOT*DIMD];        // t  P16
__device__ __half g_xlp[MTOT*DIMD];        // x*l3 P16
__device__ __half g_wB [5*DIMD*DIMD];      // weights B16 (w1 uses 2 blocks)
#define W1B 0
#define W2B (2*DIMD*DIMD)
#define W3B (3*DIMD*DIMD)
#define W4B (4*DIMD*DIMD)

// ---------------- helpers ---------------------------------------------------
__device__ __forceinline__ float gelu_exact(float v){ return v * normcdff(v); }
__device__ __forceinline__ uint32_t h2(float lo, float hi){
    __half2 h = __floats2half2_rn(lo, hi);
    return *(uint32_t*)&h;
}
__device__ __forceinline__ float h1r(float x){
    return __half2float(__float2half_rn(x));
}
__device__ __forceinline__ uint32_t smem_u32(const void* p){
    uint32_t a; asm("{ .reg .u64 t; cvta.to.shared.u64 t, %1; cvt.u32.u64 %0, t; }" : "=r"(a) : "l"(p));
    return a;
}
__device__ __forceinline__ void cpa16(uint32_t dst, const void* src){
    asm volatile("cp.async.cg.shared.global [%0], [%1], 16;" :: "r"(dst), "l"(src));
}
__device__ __forceinline__ void cpa_commit(){ asm volatile("cp.async.commit_group;"); }
__device__ __forceinline__ void cpa_wait1(){ asm volatile("cp.async.wait_group 1;"); }

__device__ __forceinline__ void mma16(float* cc, const uint32_t* a, const uint32_t* b){
    asm volatile("mma.sync.aligned.m16n8k16.row.col.f32.f16.f16.f32 "
       "{%0,%1,%2,%3},{%4,%5,%6,%7},{%8,%9},{%0,%1,%2,%3};"
       : "+f"(cc[0]),"+f"(cc[1]),"+f"(cc[2]),"+f"(cc[3])
       : "r"(a[0]),"r"(a[1]),"r"(a[2]),"r"(a[3]),"r"(b[0]),"r"(b[1]));
}

// GEMM smem: 3 stages x (A 8KB + B 8KB) = 48KB  (BK = 32)
#define STG 8192u
#define SBOFF 24576u
#define DSMEM_SZ 49152
// GRAM smem: 3 stages x (A 16KB + B 16KB) = 96KB (BK = 64)
#define GSTG 16384u
#define GSBOFF 49152u
#define DSMEM_GRAM 98304
#define LN_SMEM (16*772*4)

// ---------------------------------------------------------------- k_avg
__global__ void k_avg1(const float* __restrict__ x){
    int chunk = blockIdx.x, b = blockIdx.y;
    int t = threadIdx.x;
    const float4* p = (const float4*)(x + ((size_t)b*NTOK + chunk*128)*DIMD) + t;
    float4 s = make_float4(0.f,0.f,0.f,0.f);
    #pragma unroll 4
    for (int i=0;i<128;i++){
        float4 v = p[i*(DIMD/4)];
        s.x+=v.x; s.y+=v.y; s.z+=v.z; s.w+=v.w;
    }
    *((float4*)(g_pav + ((size_t)chunk*NB + b)*DIMD) + t) = s;
}
__global__ void k_avg2(){
    int gid = blockIdx.x*256 + threadIdx.x;
    int b = gid / DIMD, d = gid % DIMD;
    float s = 0.f;
    #pragma unroll
    for (int c=0;c<8;c++) s += g_pav[((size_t)c*NB + b)*DIMD + d];
    g_avg[gid] = s * (1.0f/NTOK);
}

// ---------------------------------------------------------------- k_ln
// A = fp16(avg*sigmoid(LN(x))) -> g_cat (P16 lower K) + g_Ab (B16)
__global__ void __launch_bounds__(256) k_ln(const float* __restrict__ x,
                                            const float* __restrict__ gamma,
                                            const float* __restrict__ beta){
    extern __shared__ float s[];               // 16 x 772
    int tb = blockIdx.x;
    int tid = threadIdx.x, w = tid>>5, l = tid&31;
    #pragma unroll
    for (int half=0; half<2; half++){
        int trow = w*2 + half;
        int tok  = tb*16 + trow;
        const float* xp = x + (size_t)tok*DIMD;
        float v[24]; float s1=0.f, s2=0.f;
        #pragma unroll
        for (int i=0;i<24;i++){ v[i]=xp[l+32*i]; s1+=v[i]; s2+=v[i]*v[i]; }
        #pragma unroll
        for (int o=16;o;o>>=1){ s1+=__shfl_xor_sync(~0u,s1,o); s2+=__shfl_xor_sync(~0u,s2,o); }
        float mu  = s1*(1.f/DIMD);
        float var = s2*(1.f/DIMD) - mu*mu;
        float rs  = rsqrtf(var + 1e-5f);
        const float* av = g_avg + (tok>>10)*DIMD;
        float asq = 0.f;
        #pragma unroll
        for (int i=0;i<24;i++){
            int d = l + 32*i;
            float y  = (v[i]-mu)*rs*gamma[d] + beta[d];
            float sg = 1.f/(1.f+expf(-y));
            float a  = h1r(av[d]*sg);
            s[trow*772 + d] = a;
            asq += a*a;
        }
        #pragma unroll
        for (int o=16;o;o>>=1) asq += __shfl_xor_sync(~0u,asq,o);
        if (l==0){ g_sq[tok]=asq; g_m[tok]=0.f; }
    }
    __syncthreads();
    int rr = l>>2, c2 = (l&3)*2;
    // P16 store (lower K half of g_cat)
    #pragma unroll
    for (int it=0; it<6; it++){
        int ksub = it*8 + w;                   // 0..47
        int kk = ksub*16 + c2;
        uint4 o;
        o.x = h2(s[rr*772+kk],       s[rr*772+kk+1]);
        o.y = h2(s[(rr+8)*772+kk],   s[(rr+8)*772+kk+1]);
        o.z = h2(s[rr*772+kk+8],     s[rr*772+kk+9]);
        o.w = h2(s[(rr+8)*772+kk+8], s[(rr+8)*772+kk+9]);
        *(uint4*)(g_cat + ((size_t)tb*96 + ksub)*256 + l*8) = o;
    }
    // B16 store: subtile=8 n x 16 k, lane word = 4 halfs
    #pragma unroll
    for (int it=0; it<12; it++){
        int subidx = it*8 + w;                 // 0..95
        int nsub = subidx/48, ksub = subidx%48;
        int n = nsub*8 + rr;
        int kk = ksub*16 + c2;
        uint2 o;
        o.x = h2(s[n*772+kk],   s[n*772+kk+1]);
        o.y = h2(s[n*772+kk+8], s[n*772+kk+9]);
        *(uint2*)(g_Ab + (((size_t)(tb*2+nsub))*48 + ksub)*128 + l*4) = o;
    }
}

// ---------------------------------------------------------------- k_xm
// upper half of g_cat = fp16(x+m) P16; folds w1 -> B16 transpose
__global__ void __launch_bounds__(256) k_xm(const float* __restrict__ x,
                                            const float* __restrict__ w1){
    extern __shared__ float s[];   // 16 x 772
    int tb = blockIdx.x;
    int tid = threadIdx.x;
    #pragma unroll
    for (int it=0; it<12; it++){
        int idx = it*256 + tid;
        int row = idx/192, c4 = idx%192;
        int tok = tb*16 + row;
        float4 v = *(const float4*)(x + (size_t)tok*DIMD + c4*4);
        float mm = g_m[tok];
        float* d = s + row*772 + c4*4;
        d[0]=v.x+mm; d[1]=v.y+mm; d[2]=v.z+mm; d[3]=v.w+mm;
    }
    __syncthreads();
    int w = tid>>5, l = tid&31;
    int rr = l>>2, c2 = (l&3)*2;
    #pragma unroll
    for (int it=0; it<6; it++){
        int ksub = it*8 + w;
        int kk = ksub*16 + c2;
        uint4 o;
        o.x = h2(s[rr*772+kk],       s[rr*772+kk+1]);
        o.y = h2(s[(rr+8)*772+kk],   s[(rr+8)*772+kk+1]);
        o.z = h2(s[rr*772+kk+8],     s[rr*772+kk+9]);
        o.w = h2(s[(rr+8)*772+kk+8], s[(rr+8)*772+kk+9]);
        *(uint4*)(g_cat + ((size_t)tb*96 + 48 + ksub)*256 + l*8) = o;
    }
    // folded w1 -> B16 (K=1536): 288 8B-words per block
    #pragma unroll
    for (int it=0; it<2; it++){
        int off = it*256 + tid;
        if (off < 288){
            size_t wd = (size_t)tb*288 + off;
            int sub = (int)(wd>>5), lane = (int)(wd&31);
            int n = (sub/96)*8 + (lane>>2);
            int kk = (sub%96)*16 + (lane&3)*2;
            uint2 o;
            o.x = h2(w1[(size_t)kk*DIMD+n],     w1[(size_t)(kk+1)*DIMD+n]);
            o.y = h2(w1[(size_t)(kk+8)*DIMD+n], w1[(size_t)(kk+9)*DIMD+n]);
            *(uint2*)(g_wB + W1B + wd*4) = o;
        }
    }
}

// ---------------------------------------------------------------- k_tr_rest
__global__ void k_tr_rest(const float* __restrict__ w2,
                          const float* __restrict__ w3,
                          const float* __restrict__ w4){
    int z = blockIdx.y;
    const float* wsrc = (z==0)? w2 : (z==1)? w3 : w4;
    __half* dst = g_wB + ((z==0)? W2B : (z==1)? W3B : W4B);
    size_t wd = (size_t)blockIdx.x*256 + threadIdx.x;
    int sub = (int)(wd>>5), lane = (int)(wd&31);
    int n = (sub/48)*8 + (lane>>2);
    int kk = (sub%48)*16 + (lane&3)*2;
    uint2 o;
    o.x = h2(wsrc[(size_t)kk*DIMD+n],     wsrc[(size_t)(kk+1)*DIMD+n]);
    o.y = h2(wsrc[(size_t)(kk+8)*DIMD+n], wsrc[(size_t)(kk+9)*DIMD+n]);
    *(uint2*)(dst + wd*4) = o;
}

// ---------------------------------------------------------------- k_gemm (BK=32, R11 exact)
// EPI 0: gelu   1: gelu*x*m1 (m1 from P16 buffer)   2: gelu*x
// OUT 1: Cp=P16   2: Cr=raw row
template<int EPI, int OUT>
__global__ void __launch_bounds__(256) k_gemm(
    const __half* __restrict__ pA, const __half* __restrict__ pB,
    const float* __restrict__ bias, const float* __restrict__ x,
    const __half* __restrict__ m1h, __half* __restrict__ Cp,
    float* __restrict__ Cr, int Ktot)
{
    extern __shared__ float dsm[];
    uint32_t sA = smem_u32(dsm);
    uint32_t sB = sA + SBOFF;
    int tid = threadIdx.x, lane = tid&31;
    int wm = (tid>>5)&1, wn = tid>>6;
    int r = lane>>2, c = lane&3;
    int nb = blockIdx.x, mb = blockIdx.y;
    const int KT  = Ktot/32;
    const int K16 = Ktot>>4;

    float acc[4][4][4];
    #pragma unroll
    for (int a=0;a<4;a++)
      #pragma unroll
      for (int b=0;b<4;b++)
        #pragma unroll
        for (int e=0;e<4;e++) acc[a][b][e]=0.f;

    auto load_stage = [&](int kt){
        int st = kt % 3;
        uint32_t dA = sA + st*STG;
        uint32_t dB = sB + st*STG;
        #pragma unroll
        for (int it=0; it<2; it++){
            int wd = it*256 + tid;             // 0..511
            int rowsub = wd>>6, remA = wd&63;
            cpa16(dA + wd*16, pA + ((size_t)(mb*8+rowsub)*K16 + kt*2)*256 + remA*8);
            int nsub = wd>>5,  remB = wd&31;
            cpa16(dB + wd*16, pB + ((size_t)(nb*16+nsub)*K16 + kt*2)*128 + remB*8);
        }
        cpa_commit();
    };

    load_stage(0); load_stage(1);
    for (int kt=0; kt<KT; kt++){
        cpa_wait1();
        __syncthreads();
        if (kt+2 < KT) load_stage(kt+2); else cpa_commit();
        int st = kt % 3;
        uint32_t bA = sA + st*STG;
        uint32_t bB = sB + st*STG;
        #pragma unroll
        for (int jj=0;jj<2;jj++){
            uint4 af[4]; uint2 bf[4];
            #pragma unroll
            for (int mt=0;mt<4;mt++){
                uint32_t a = bA + (((wm*4+mt)*2+jj)<<9) + (lane<<4);
                asm volatile("ld.shared.v4.b32 {%0,%1,%2,%3},[%4];"
                  : "=r"(af[mt].x),"=r"(af[mt].y),"=r"(af[mt].z),"=r"(af[mt].w) : "r"(a));
            }
            #pragma unroll
            for (int nt=0;nt<4;nt++){
                uint32_t a = bB + (((wn*4+nt)*2+jj)<<8) + (lane<<3);
                asm volatile("ld.shared.v2.b32 {%0,%1},[%2];"
                  : "=r"(bf[nt].x),"=r"(bf[nt].y) : "r"(a));
            }
            #pragma unroll
            for (int mt=0;mt<4;mt++)
                #pragma unroll
                for (int nt=0;nt<4;nt++)
                    mma16(acc[mt][nt], &af[mt].x, &bf[nt].x);
        }
    }

    // epilogue
    #pragma unroll
    for (int mt=0; mt<4; mt++){
        int rp = mb*128 + wm*64 + mt*16 + r;
        float val[4][4];
        uint4 mws[2];
        if (EPI==1){
            #pragma unroll
            for (int ntp=0; ntp<2; ntp++)
                mws[ntp] = *(const uint4*)(m1h +
                    (((size_t)(mb*8+wm*4+mt))*48 + nb*8+wn*2+ntp)*256 + lane*8);
        }
        #pragma unroll
        for (int nt=0; nt<4; nt++){
            int cg = nb*128 + wn*32 + nt*8 + 2*c;
            float bb0 = __ldg(bias+cg), bb1 = __ldg(bias+cg+1);
            float a0 = gelu_exact(acc[mt][nt][0] + bb0);
            float a1 = gelu_exact(acc[mt][nt][1] + bb1);
            float a2 = gelu_exact(acc[mt][nt][2] + bb0);
            float a3 = gelu_exact(acc[mt][nt][3] + bb1);
            size_t i0 = (size_t)rp*DIMD + cg, i1 = (size_t)(rp+8)*DIMD + cg;
            if (EPI==1){
                uint32_t lo = (nt&1)? mws[nt>>1].z : mws[nt>>1].x;
                uint32_t hi = (nt&1)? mws[nt>>1].w : mws[nt>>1].y;
                float2 m0 = __half22float2(*(__half2*)&lo);
                float2 m1v= __half22float2(*(__half2*)&hi);
                float2 xa=*(const float2*)(x+i0),  xb=*(const float2*)(x+i1);
                a0*=xa.x*m0.x; a1*=xa.y*m0.y; a2*=xb.x*m1v.x; a3*=xb.y*m1v.y;
            } else if (EPI==2){
                float2 xa=*(const float2*)(x+i0), xb=*(const float2*)(x+i1);
                a0*=xa.x; a1*=xa.y; a2*=xb.x; a3*=xb.y;
            }
            if (OUT==2){
                *(float2*)(Cr+i0) = make_float2(a0,a1);
                *(float2*)(Cr+i1) = make_float2(a2,a3);
            }
            val[nt][0]=a0; val[nt][1]=a1; val[nt][2]=a2; val[nt][3]=a3;
        }
        if (OUT==1){
            #pragma unroll
            for (int ntp=0; ntp<2; ntp++){
                uint4 o;
                o.x = h2(val[2*ntp][0],   val[2*ntp][1]);
                o.y = h2(val[2*ntp][2],   val[2*ntp][3]);
                o.z = h2(val[2*ntp+1][0], val[2*ntp+1][1]);
                o.w = h2(val[2*ntp+1][2], val[2*ntp+1][3]);
                *(uint4*)(Cp + (((size_t)(mb*8+wm*4+mt))*48 + nb*8+wn*2+ntp)*256 + lane*8) = o;
            }
        }
    }
}

// ---------------------------------------------------------------- k_gram (BK=64, R9 mainloop)
__global__ void __launch_bounds__(256) k_gram(){
    extern __shared__ float dsm[];
    uint32_t sA = smem_u32(dsm);
    uint32_t sB = sA + GSBOFF;
    __shared__ int   smax_i[128], smax_j[128];
    __shared__ float sqi_s[128], sqj_s[128];

    int tid = threadIdx.x, lane = tid&31;
    int wm = (tid>>5)&1, wn = tid>>6;
    int r = lane>>2, c = lane&3;
    int b = blockIdx.y;
    int tt = blockIdx.x, ib = 0;
    while (tt >= (8-ib)){ tt -= (8-ib); ib++; }
    int jb = ib + tt;

    if (tid<128){
        sqi_s[tid] = g_sq[b*NTOK + ib*128 + tid];
        sqj_s[tid] = g_sq[b*NTOK + jb*128 + tid];
        smax_i[tid]=0; smax_j[tid]=0;
    }

    float acc[4][4][4];
    #pragma unroll
    for (int a=0;a<4;a++)
      #pragma unroll
      for (int bb=0;bb<4;bb++)
        #pragma unroll
        for (int e=0;e<4;e++) acc[a][bb][e]=0.f;

    const int KT = DIMD/64;   // 12
    auto load_stage = [&](int kt){
        int st = kt % 3;
        uint32_t dA = sA + st*GSTG;
        uint32_t dB = sB + st*GSTG;
        #pragma unroll
        for (int it=0; it<4; it++){
            int wd = it*256 + tid;             // 0..1023
            int rowsub = wd>>7, remA = wd&127;
            cpa16(dA + wd*16, g_cat + ((size_t)(b*64+ib*8+rowsub)*96 + kt*4)*256 + remA*8);
            int nsub = wd>>6,  remB = wd&63;
            cpa16(dB + wd*16, g_Ab + ((size_t)(b*128+jb*16+nsub)*48 + kt*4)*128 + remB*8);
        }
        cpa_commit();
    };

    load_stage(0); load_stage(1);
    for (int kt=0; kt<KT; kt++){
        cpa_wait1();
        __syncthreads();
        if (kt+2 < KT) load_stage(kt+2); else cpa_commit();
        int st = kt % 3;
        uint32_t bA = sA + st*GSTG;
        uint32_t bB = sB + st*GSTG;
        #pragma unroll
        for (int jj=0;jj<4;jj++){
            uint4 af[4]; uint2 bf[4];
            #pragma unroll
            for (int mt=0;mt<4;mt++){
                uint32_t a = bA + (((wm*4+mt)*4+jj)<<9) + (lane<<4);
                asm volatile("ld.shared.v4.b32 {%0,%1,%2,%3},[%4];"
                  : "=r"(af[mt].x),"=r"(af[mt].y),"=r"(af[mt].z),"=r"(af[mt].w) : "r"(a));
            }
            #pragma unroll
            for (int nt=0;nt<4;nt++){
                uint32_t a = bB + (((wn*4+nt)*4+jj)<<8) + (lane<<3);
                asm volatile("ld.shared.v2.b32 {%0,%1},[%2];"
                  : "=r"(bf[nt].x),"=r"(bf[nt].y) : "r"(a));
            }
            #pragma unroll
            for (int mt=0;mt<4;mt++)
                #pragma unroll
                for (int nt=0;nt<4;nt++)
                    mma16(acc[mt][nt], &af[mt].x, &bf[nt].x);
        }
    }

    float rmax[8], cmax[8];
    #pragma unroll
    for (int i=0;i<8;i++){ rmax[i]=0.f; cmax[i]=0.f; }
    #pragma unroll
    for (int mt=0; mt<4; mt++){
        #pragma unroll
        for (int i2=0; i2<2; i2++){
            int rl = wm*64 + mt*16 + r + i2*8;
            float si = sqi_s[rl];
            #pragma unroll
            for (int nt=0; nt<4; nt++){
                #pragma unroll
                for (int q=0; q<2; q++){
                    int cl = wn*32 + nt*8 + 2*c + q;
                    float d2 = si + sqj_s[cl] - 2.f*acc[mt][nt][i2*2+q];
                    float dd = sqrtf(fmaxf(d2, 1e-12f));
                    rmax[mt*2+i2] = fmaxf(rmax[mt*2+i2], dd);
                    cmax[nt*2+q]  = fmaxf(cmax[nt*2+q],  dd);
                }
            }
        }
    }
    #pragma unroll
    for (int mt=0; mt<4; mt++)
        #pragma unroll
        for (int i2=0; i2<2; i2++)
            atomicMax(&smax_i[wm*64+mt*16+r+i2*8], __float_as_int(rmax[mt*2+i2]));
    #pragma unroll
    for (int nt=0; nt<4; nt++)
        #pragma unroll
        for (int q=0; q<2; q++)
            atomicMax(&smax_j[wn*32+nt*8+2*c+q], __float_as_int(cmax[nt*2+q]));
    __syncthreads();
    if (tid<128){
        atomicMax((int*)&g_m[b*NTOK + ib*128 + tid], smax_i[tid]);
        atomicMax((int*)&g_m[b*NTOK + jb*128 + tid], smax_j[tid]);
    }
}

// ---------------------------------------------------------------- launch
extern "C" void kernel_launch(void* const* d_in, const int* in_sizes, int n_in,
                              void* d_out, int out_size) {
    const float* x     = (const float*)d_in[0];
    const float* gamma = (const float*)d_in[1];
    const float* beta  = (const float*)d_in[2];
    const float* w1 = (const float*)d_in[3];
    const float* b1 = (const float*)d_in[4];
    const float* w2 = (const float*)d_in[5];
    const float* b2 = (const float*)d_in[6];
    const float* w3 = (const float*)d_in[7];
    const float* b3 = (const float*)d_in[8];
    const float* w4 = (const float*)d_in[9];
    const float* b4 = (const float*)d_in[10];
    float* out = (float*)d_out;

    cudaFuncSetAttribute(k_gram,      cudaFuncAttributeMaxDynamicSharedMemorySize, DSMEM_GRAM);
    cudaFuncSetAttribute(k_ln,        cudaFuncAttributeMaxDynamicSharedMemorySize, LN_SMEM);
    cudaFuncSetAttribute(k_xm,        cudaFuncAttributeMaxDynamicSharedMemorySize, LN_SMEM);
    cudaFuncSetAttribute(k_gemm<0,1>, cudaFuncAttributeMaxDynamicSharedMemorySize, DSMEM_SZ);
    cudaFuncSetAttribute(k_gemm<1,1>, cudaFuncAttributeMaxDynamicSharedMemorySize, DSMEM_SZ);
    cudaFuncSetAttribute(k_gemm<2,1>, cudaFuncAttributeMaxDynamicSharedMemorySize, DSMEM_SZ);
    cudaFuncSetAttribute(k_gemm<0,2>, cudaFuncAttributeMaxDynamicSharedMemorySize, DSMEM_SZ);

    __half *wB, *cat, *m1p, *tp, *xlp;
    cudaGetSymbolAddress((void**)&wB,  g_wB);
    cudaGetSymbolAddress((void**)&cat, g_cat);
    cudaGetSymbolAddress((void**)&m1p, g_m1p);
    cudaGetSymbolAddress((void**)&tp,  g_tp);
    cudaGetSymbolAddress((void**)&xlp, g_xlp);

    k_avg1<<<dim3(8, NB), 192>>>(x);
    k_avg2<<<MTOT*DIMD/NTOK/256, 256>>>();
    k_ln  <<<MTOT/16, 256, LN_SMEM>>>(x, gamma, beta);
    k_gram<<<dim3(36, NB), 256, DSMEM_GRAM>>>();
    k_xm  <<<MTOT/16, 256, LN_SMEM>>>(x, w1);

    dim3 gg(DIMD/128, MTOT/128);
    // layer1: m1 = gelu(cat @ w1 + b1)            -> m1p (P16 only)
    k_gemm<0,1><<<gg,256,DSMEM_SZ>>>(cat, wB+W1B, b1, x, nullptr, m1p, nullptr, 2*DIMD);
    k_tr_rest<<<dim3(576, 3), 256>>>(w2, w3, w4);
    // layer2: t = x*m1*gelu(m1 @ w2 + b2)         -> tp (P16); m1 gating from m1p
    k_gemm<1,1><<<gg,256,DSMEM_SZ>>>(m1p, wB+W2B, b2, x, m1p,    tp,  nullptr, DIMD);
    // layer3: x*l3 = x*gelu(t @ w3 + b3)          -> xlp (P16)
    k_gemm<2,1><<<gg,256,DSMEM_SZ>>>(tp,  wB+W3B, b3, x, nullptr, xlp, nullptr, DIMD);
    // layer4: out = gelu((x*l3) @ w4 + b4)        -> out (row fp32)
    k_gemm<0,2><<<gg,256,DSMEM_SZ>>>(xlp, wB+W4B, b4, x, nullptr, nullptr, out, DIMD);
}

// round 17
// speedup vs baseline: 1.0800x; 1.0378x over previous
#include <cuda_runtime.h>
#include <cuda_fp16.h>
#include <math.h>
#include <stdint.h>

#define DIMD 768
#define NTOK 1024
#define NB   16
#define MTOT (NB*NTOK)   // 16384

// ---------------- scratch (static device globals) --------------------------
__device__ float g_avg[NB*DIMD];
__device__ float g_pav[8*NB*DIMD];
__device__ float g_sq [MTOT];
__device__ float g_m  [MTOT];            // holds max d2 (clipped); sqrt applied in k_xm
__device__ __half g_cat[MTOT*2*DIMD];    // [A | x+m] P16-format, K=1536
__device__ __half g_Ab [MTOT*DIMD];      // A B16-format (gram j-side)
__device__ __half g_m1p[MTOT*DIMD];      // m1 P16 (also gating source)
__device__ __half g_tp [MTOT*DIMD];      // t  P16
__device__ __half g_xlp[MTOT*DIMD];      // x*l3 P16
__device__ __half g_wB [5*DIMD*DIMD];    // weights B16 (w1 uses 2 blocks)
#define W1B 0
#define W2B (2*DIMD*DIMD)
#define W3B (3*DIMD*DIMD)
#define W4B (4*DIMD*DIMD)

// ---------------- helpers ---------------------------------------------------
__device__ __forceinline__ float gelu_exact(float v){ return v * normcdff(v); }
__device__ __forceinline__ uint32_t h2(float lo, float hi){
    __half2 h = __floats2half2_rn(lo, hi);
    return *(uint32_t*)&h;
}
__device__ __forceinline__ float h1r(float x){
    return __half2float(__float2half_rn(x));
}
__device__ __forceinline__ uint32_t smem_u32(const void* p){
    uint32_t a; asm("{ .reg .u64 t; cvta.to.shared.u64 t, %1; cvt.u32.u64 %0, t; }" : "=r"(a) : "l"(p));
    return a;
}
__device__ __forceinline__ void cpa16(uint32_t dst, const void* src){
    asm volatile("cp.async.cg.shared.global [%0], [%1], 16;" :: "r"(dst), "l"(src));
}
__device__ __forceinline__ void cpa_commit(){ asm volatile("cp.async.commit_group;"); }
__device__ __forceinline__ void cpa_wait1(){ asm volatile("cp.async.wait_group 1;"); }

__device__ __forceinline__ void mma16(float* cc, const uint32_t* a, const uint32_t* b){
    asm volatile("mma.sync.aligned.m16n8k16.row.col.f32.f16.f16.f32 "
       "{%0,%1,%2,%3},{%4,%5,%6,%7},{%8,%9},{%0,%1,%2,%3};"
       : "+f"(cc[0]),"+f"(cc[1]),"+f"(cc[2]),"+f"(cc[3])
       : "r"(a[0]),"r"(a[1]),"r"(a[2]),"r"(a[3]),"r"(b[0]),"r"(b[1]));
}

// GEMM smem: 3 stages x (A 8KB + B 8KB) = 48KB  (BK = 32)
#define STG 8192u
#define SBOFF 24576u
#define DSMEM_SZ 49152
// GRAM smem: 3 stages x (A 16KB + B 16KB) = 96KB (BK = 64)
#define GSTG 16384u
#define GSBOFF 49152u
#define DSMEM_GRAM 98304
#define LN_SMEM (16*772*4)

// ---------------------------------------------------------------- k_avg
__global__ void k_avg1(const float* __restrict__ x){
    int chunk = blockIdx.x, b = blockIdx.y;
    int t = threadIdx.x;
    const float4* p = (const float4*)(x + ((size_t)b*NTOK + chunk*128)*DIMD) + t;
    float4 s = make_float4(0.f,0.f,0.f,0.f);
    #pragma unroll 4
    for (int i=0;i<128;i++){
        float4 v = p[i*(DIMD/4)];
        s.x+=v.x; s.y+=v.y; s.z+=v.z; s.w+=v.w;
    }
    *((float4*)(g_pav + ((size_t)chunk*NB + b)*DIMD) + t) = s;
}
__global__ void k_avg2(){
    int gid = blockIdx.x*256 + threadIdx.x;
    int b = gid / DIMD, d = gid % DIMD;
    float s = 0.f;
    #pragma unroll
    for (int c=0;c<8;c++) s += g_pav[((size_t)c*NB + b)*DIMD + d];
    g_avg[gid] = s * (1.0f/NTOK);
}

// ---------------------------------------------------------------- k_ln
// A = fp16(avg*sigmoid(LN(x))) -> g_cat (P16 lower K) + g_Ab (B16)
// x loads vectorized (float4); element remap only reassociates the LN sums.
__global__ void __launch_bounds__(256) k_ln(const float* __restrict__ x,
                                            const float* __restrict__ gamma,
                                            const float* __restrict__ beta){
    extern __shared__ float s[];               // 16 x 772
    int tb = blockIdx.x;
    int tid = threadIdx.x, w = tid>>5, l = tid&31;
    #pragma unroll
    for (int half=0; half<2; half++){
        int trow = w*2 + half;
        int tok  = tb*16 + trow;
        const float4* xp4 = (const float4*)(x + (size_t)tok*DIMD);
        float4 v4[6]; float s1=0.f, s2=0.f;
        #pragma unroll
        for (int i=0;i<6;i++){
            v4[i] = xp4[l + 32*i];
            s1 += v4[i].x+v4[i].y+v4[i].z+v4[i].w;
            s2 += v4[i].x*v4[i].x + v4[i].y*v4[i].y + v4[i].z*v4[i].z + v4[i].w*v4[i].w;
        }
        #pragma unroll
        for (int o=16;o;o>>=1){ s1+=__shfl_xor_sync(~0u,s1,o); s2+=__shfl_xor_sync(~0u,s2,o); }
        float mu  = s1*(1.f/DIMD);
        float var = s2*(1.f/DIMD) - mu*mu;
        float rs  = rsqrtf(var + 1e-5f);
        const float* av = g_avg + (tok>>10)*DIMD;
        float asq = 0.f;
        #pragma unroll
        for (int i=0;i<6;i++){
            int d0 = (l + 32*i)*4;
            float vv[4] = {v4[i].x, v4[i].y, v4[i].z, v4[i].w};
            #pragma unroll
            for (int q=0;q<4;q++){
                int d = d0 + q;
                float y  = (vv[q]-mu)*rs*gamma[d] + beta[d];
                float sg = 1.f/(1.f+expf(-y));
                float a  = h1r(av[d]*sg);
                s[trow*772 + d] = a;
                asq += a*a;
            }
        }
        #pragma unroll
        for (int o=16;o;o>>=1) asq += __shfl_xor_sync(~0u,asq,o);
        if (l==0){ g_sq[tok]=asq; g_m[tok]=0.f; }
    }
    __syncthreads();
    int rr = l>>2, c2 = (l&3)*2;
    // P16 store (lower K half of g_cat)
    #pragma unroll
    for (int it=0; it<6; it++){
        int ksub = it*8 + w;                   // 0..47
        int kk = ksub*16 + c2;
        uint4 o;
        o.x = h2(s[rr*772+kk],       s[rr*772+kk+1]);
        o.y = h2(s[(rr+8)*772+kk],   s[(rr+8)*772+kk+1]);
        o.z = h2(s[rr*772+kk+8],     s[rr*772+kk+9]);
        o.w = h2(s[(rr+8)*772+kk+8], s[(rr+8)*772+kk+9]);
        *(uint4*)(g_cat + ((size_t)tb*96 + ksub)*256 + l*8) = o;
    }
    // B16 store: subtile=8 n x 16 k, lane word = 4 halfs
    #pragma unroll
    for (int it=0; it<12; it++){
        int subidx = it*8 + w;                 // 0..95
        int nsub = subidx/48, ksub = subidx%48;
        int n = nsub*8 + rr;
        int kk = ksub*16 + c2;
        uint2 o;
        o.x = h2(s[n*772+kk],   s[n*772+kk+1]);
        o.y = h2(s[n*772+kk+8], s[n*772+kk+9]);
        *(uint2*)(g_Ab + (((size_t)(tb*2+nsub))*48 + ksub)*128 + l*4) = o;
    }
}

// ---------------------------------------------------------------- k_xm
// upper half of g_cat = fp16(x+m) P16; m = sqrt(max-d2 from gram); folds w1 -> B16
__global__ void __launch_bounds__(256) k_xm(const float* __restrict__ x,
                                            const float* __restrict__ w1){
    extern __shared__ float s[];   // 16 x 772
    int tb = blockIdx.x;
    int tid = threadIdx.x;
    #pragma unroll
    for (int it=0; it<12; it++){
        int idx = it*256 + tid;
        int row = idx/192, c4 = idx%192;
        int tok = tb*16 + row;
        float4 v = *(const float4*)(x + (size_t)tok*DIMD + c4*4);
        float mm = sqrtf(g_m[tok]);            // sqrt hoisted out of gram epilogue
        float* d = s + row*772 + c4*4;
        d[0]=v.x+mm; d[1]=v.y+mm; d[2]=v.z+mm; d[3]=v.w+mm;
    }
    __syncthreads();
    int w = tid>>5, l = tid&31;
    int rr = l>>2, c2 = (l&3)*2;
    #pragma unroll
    for (int it=0; it<6; it++){
        int ksub = it*8 + w;
        int kk = ksub*16 + c2;
        uint4 o;
        o.x = h2(s[rr*772+kk],       s[rr*772+kk+1]);
        o.y = h2(s[(rr+8)*772+kk],   s[(rr+8)*772+kk+1]);
        o.z = h2(s[rr*772+kk+8],     s[rr*772+kk+9]);
        o.w = h2(s[(rr+8)*772+kk+8], s[(rr+8)*772+kk+9]);
        *(uint4*)(g_cat + ((size_t)tb*96 + 48 + ksub)*256 + l*8) = o;
    }
    // folded w1 -> B16 (K=1536): 288 8B-words per block
    #pragma unroll
    for (int it=0; it<2; it++){
        int off = it*256 + tid;
        if (off < 288){
            size_t wd = (size_t)tb*288 + off;
            int sub = (int)(wd>>5), lane = (int)(wd&31);
            int n = (sub/96)*8 + (lane>>2);
            int kk = (sub%96)*16 + (lane&3)*2;
            uint2 o;
            o.x = h2(w1[(size_t)kk*DIMD+n],     w1[(size_t)(kk+1)*DIMD+n]);
            o.y = h2(w1[(size_t)(kk+8)*DIMD+n], w1[(size_t)(kk+9)*DIMD+n]);
            *(uint2*)(g_wB + W1B + wd*4) = o;
        }
    }
}

// ---------------------------------------------------------------- k_tr_rest
__global__ void k_tr_rest(const float* __restrict__ w2,
                          const float* __restrict__ w3,
                          const float* __restrict__ w4){
    int z = blockIdx.y;
    const float* wsrc = (z==0)? w2 : (z==1)? w3 : w4;
    __half* dst = g_wB + ((z==0)? W2B : (z==1)? W3B : W4B);
    size_t wd = (size_t)blockIdx.x*256 + threadIdx.x;
    int sub = (int)(wd>>5), lane = (int)(wd&31);
    int n = (sub/48)*8 + (lane>>2);
    int kk = (sub%48)*16 + (lane&3)*2;
    uint2 o;
    o.x = h2(wsrc[(size_t)kk*DIMD+n],     wsrc[(size_t)(kk+1)*DIMD+n]);
    o.y = h2(wsrc[(size_t)(kk+8)*DIMD+n], wsrc[(size_t)(kk+9)*DIMD+n]);
    *(uint2*)(dst + wd*4) = o;
}

// ---------------------------------------------------------------- k_gemm (BK=32, R11 exact)
// EPI 0: gelu   1: gelu*x*m1 (m1 from P16 buffer)   2: gelu*x
// OUT 1: Cp=P16   2: Cr=raw row
template<int EPI, int OUT>
__global__ void __launch_bounds__(256) k_gemm(
    const __half* __restrict__ pA, const __half* __restrict__ pB,
    const float* __restrict__ bias, const float* __restrict__ x,
    const __half* __restrict__ m1h, __half* __restrict__ Cp,
    float* __restrict__ Cr, int Ktot)
{
    extern __shared__ float dsm[];
    uint32_t sA = smem_u32(dsm);
    uint32_t sB = sA + SBOFF;
    int tid = threadIdx.x, lane = tid&31;
    int wm = (tid>>5)&1, wn = tid>>6;
    int r = lane>>2, c = lane&3;
    int nb = blockIdx.x, mb = blockIdx.y;
    const int KT  = Ktot/32;
    const int K16 = Ktot>>4;

    float acc[4][4][4];
    #pragma unroll
    for (int a=0;a<4;a++)
      #pragma unroll
      for (int b=0;b<4;b++)
        #pragma unroll
        for (int e=0;e<4;e++) acc[a][b][e]=0.f;

    auto load_stage = [&](int kt){
        int st = kt % 3;
        uint32_t dA = sA + st*STG;
        uint32_t dB = sB + st*STG;
        #pragma unroll
        for (int it=0; it<2; it++){
            int wd = it*256 + tid;             // 0..511
            int rowsub = wd>>6, remA = wd&63;
            cpa16(dA + wd*16, pA + ((size_t)(mb*8+rowsub)*K16 + kt*2)*256 + remA*8);
            int nsub = wd>>5,  remB = wd&31;
            cpa16(dB + wd*16, pB + ((size_t)(nb*16+nsub)*K16 + kt*2)*128 + remB*8);
        }
        cpa_commit();
    };

    load_stage(0); load_stage(1);
    for (int kt=0; kt<KT; kt++){
        cpa_wait1();
        __syncthreads();
        if (kt+2 < KT) load_stage(kt+2); else cpa_commit();
        int st = kt % 3;
        uint32_t bA = sA + st*STG;
        uint32_t bB = sB + st*STG;
        #pragma unroll
        for (int jj=0;jj<2;jj++){
            uint4 af[4]; uint2 bf[4];
            #pragma unroll
            for (int mt=0;mt<4;mt++){
                uint32_t a = bA + (((wm*4+mt)*2+jj)<<9) + (lane<<4);
                asm volatile("ld.shared.v4.b32 {%0,%1,%2,%3},[%4];"
                  : "=r"(af[mt].x),"=r"(af[mt].y),"=r"(af[mt].z),"=r"(af[mt].w) : "r"(a));
            }
            #pragma unroll
            for (int nt=0;nt<4;nt++){
                uint32_t a = bB + (((wn*4+nt)*2+jj)<<8) + (lane<<3);
                asm volatile("ld.shared.v2.b32 {%0,%1},[%2];"
                  : "=r"(bf[nt].x),"=r"(bf[nt].y) : "r"(a));
            }
            #pragma unroll
            for (int mt=0;mt<4;mt++)
                #pragma unroll
                for (int nt=0;nt<4;nt++)
                    mma16(acc[mt][nt], &af[mt].x, &bf[nt].x);
        }
    }

    // epilogue
    #pragma unroll
    for (int mt=0; mt<4; mt++){
        int rp = mb*128 + wm*64 + mt*16 + r;
        float val[4][4];
        uint4 mws[2];
        if (EPI==1){
            #pragma unroll
            for (int ntp=0; ntp<2; ntp++)
                mws[ntp] = *(const uint4*)(m1h +
                    (((size_t)(mb*8+wm*4+mt))*48 + nb*8+wn*2+ntp)*256 + lane*8);
        }
        #pragma unroll
        for (int nt=0; nt<4; nt++){
            int cg = nb*128 + wn*32 + nt*8 + 2*c;
            float bb0 = __ldg(bias+cg), bb1 = __ldg(bias+cg+1);
            float a0 = gelu_exact(acc[mt][nt][0] + bb0);
            float a1 = gelu_exact(acc[mt][nt][1] + bb1);
            float a2 = gelu_exact(acc[mt][nt][2] + bb0);
            float a3 = gelu_exact(acc[mt][nt][3] + bb1);
            size_t i0 = (size_t)rp*DIMD + cg, i1 = (size_t)(rp+8)*DIMD + cg;
            if (EPI==1){
                uint32_t lo = (nt&1)? mws[nt>>1].z : mws[nt>>1].x;
                uint32_t hi = (nt&1)? mws[nt>>1].w : mws[nt>>1].y;
                float2 m0 = __half22float2(*(__half2*)&lo);
                float2 m1v= __half22float2(*(__half2*)&hi);
                float2 xa=*(const float2*)(x+i0),  xb=*(const float2*)(x+i1);
                a0*=xa.x*m0.x; a1*=xa.y*m0.y; a2*=xb.x*m1v.x; a3*=xb.y*m1v.y;
            } else if (EPI==2){
                float2 xa=*(const float2*)(x+i0), xb=*(const float2*)(x+i1);
                a0*=xa.x; a1*=xa.y; a2*=xb.x; a3*=xb.y;
            }
            if (OUT==2){
                *(float2*)(Cr+i0) = make_float2(a0,a1);
                *(float2*)(Cr+i1) = make_float2(a2,a3);
            }
            val[nt][0]=a0; val[nt][1]=a1; val[nt][2]=a2; val[nt][3]=a3;
        }
        if (OUT==1){
            #pragma unroll
            for (int ntp=0; ntp<2; ntp++){
                uint4 o;
                o.x = h2(val[2*ntp][0],   val[2*ntp][1]);
                o.y = h2(val[2*ntp][2],   val[2*ntp][3]);
                o.z = h2(val[2*ntp+1][0], val[2*ntp+1][1]);
                o.w = h2(val[2*ntp+1][2], val[2*ntp+1][3]);
                *(uint4*)(Cp + (((size_t)(mb*8+wm*4+mt))*48 + nb*8+wn*2+ntp)*256 + lane*8) = o;
            }
        }
    }
}

// ---------------------------------------------------------------- k_gram (BK=64; d2-max epilogue)
__global__ void __launch_bounds__(256) k_gram(){
    extern __shared__ float dsm[];
    uint32_t sA = smem_u32(dsm);
    uint32_t sB = sA + GSBOFF;
    __shared__ int   smax_i[128], smax_j[128];
    __shared__ float sqi_s[128], sqj_s[128];

    int tid = threadIdx.x, lane = tid&31;
    int wm = (tid>>5)&1, wn = tid>>6;
    int r = lane>>2, c = lane&3;
    int b = blockIdx.y;
    int tt = blockIdx.x, ib = 0;
    while (tt >= (8-ib)){ tt -= (8-ib); ib++; }
    int jb = ib + tt;

    if (tid<128){
        sqi_s[tid] = g_sq[b*NTOK + ib*128 + tid];
        sqj_s[tid] = g_sq[b*NTOK + jb*128 + tid];
        smax_i[tid]=0; smax_j[tid]=0;
    }

    float acc[4][4][4];
    #pragma unroll
    for (int a=0;a<4;a++)
      #pragma unroll
      for (int bb=0;bb<4;bb++)
        #pragma unroll
        for (int e=0;e<4;e++) acc[a][bb][e]=0.f;

    const int KT = DIMD/64;   // 12
    auto load_stage = [&](int kt){
        int st = kt % 3;
        uint32_t dA = sA + st*GSTG;
        uint32_t dB = sB + st*GSTG;
        #pragma unroll
        for (int it=0; it<4; it++){
            int wd = it*256 + tid;             // 0..1023
            int rowsub = wd>>7, remA = wd&127;
            cpa16(dA + wd*16, g_cat + ((size_t)(b*64+ib*8+rowsub)*96 + kt*4)*256 + remA*8);
            int nsub = wd>>6,  remB = wd&63;
            cpa16(dB + wd*16, g_Ab + ((size_t)(b*128+jb*16+nsub)*48 + kt*4)*128 + remB*8);
        }
        cpa_commit();
    };

    load_stage(0); load_stage(1);
    for (int kt=0; kt<KT; kt++){
        cpa_wait1();
        __syncthreads();
        if (kt+2 < KT) load_stage(kt+2); else cpa_commit();
        int st = kt % 3;
        uint32_t bA = sA + st*GSTG;
        uint32_t bB = sB + st*GSTG;
        #pragma unroll
        for (int jj=0;jj<4;jj++){
            uint4 af[4]; uint2 bf[4];
            #pragma unroll
            for (int mt=0;mt<4;mt++){
                uint32_t a = bA + (((wm*4+mt)*4+jj)<<9) + (lane<<4);
                asm volatile("ld.shared.v4.b32 {%0,%1,%2,%3},[%4];"
                  : "=r"(af[mt].x),"=r"(af[mt].y),"=r"(af[mt].z),"=r"(af[mt].w) : "r"(a));
            }
            #pragma unroll
            for (int nt=0;nt<4;nt++){
                uint32_t a = bB + (((wn*4+nt)*4+jj)<<8) + (lane<<3);
                asm volatile("ld.shared.v2.b32 {%0,%1},[%2];"
                  : "=r"(bf[nt].x),"=r"(bf[nt].y) : "r"(a));
            }
            #pragma unroll
            for (int mt=0;mt<4;mt++)
                #pragma unroll
                for (int nt=0;nt<4;nt++)
                    mma16(acc[mt][nt], &af[mt].x, &bf[nt].x);
        }
    }

    // epilogue: max of d2 (sqrt hoisted to consumer; monotonicity => identical result)
    float rmax[8], cmax[8];
    #pragma unroll
    for (int i=0;i<8;i++){ rmax[i]=1e-12f; cmax[i]=1e-12f; }
    #pragma unroll
    for (int mt=0; mt<4; mt++){
        #pragma unroll
        for (int i2=0; i2<2; i2++){
            int rl = wm*64 + mt*16 + r + i2*8;
            float si = sqi_s[rl];
            #pragma unroll
            for (int nt=0; nt<4; nt++){
                #pragma unroll
                for (int q=0; q<2; q++){
                    int cl = wn*32 + nt*8 + 2*c + q;
                    float d2 = si + sqj_s[cl] - 2.f*acc[mt][nt][i2*2+q];
                    rmax[mt*2+i2] = fmaxf(rmax[mt*2+i2], d2);
                    cmax[nt*2+q]  = fmaxf(cmax[nt*2+q],  d2);
                }
            }
        }
    }
    #pragma unroll
    for (int mt=0; mt<4; mt++)
        #pragma unroll
        for (int i2=0; i2<2; i2++)
            atomicMax(&smax_i[wm*64+mt*16+r+i2*8], __float_as_int(rmax[mt*2+i2]));
    #pragma unroll
    for (int nt=0; nt<4; nt++)
        #pragma unroll
        for (int q=0; q<2; q++)
            atomicMax(&smax_j[wn*32+nt*8+2*c+q], __float_as_int(cmax[nt*2+q]));
    __syncthreads();
    if (tid<128){
        atomicMax((int*)&g_m[b*NTOK + ib*128 + tid], smax_i[tid]);
        atomicMax((int*)&g_m[b*NTOK + jb*128 + tid], smax_j[tid]);
    }
}

// ---------------------------------------------------------------- launch
extern "C" void kernel_launch(void* const* d_in, const int* in_sizes, int n_in,
                              void* d_out, int out_size) {
    const float* x     = (const float*)d_in[0];
    const float* gamma = (const float*)d_in[1];
    const float* beta  = (const float*)d_in[2];
    const float* w1 = (const float*)d_in[3];
    const float* b1 = (const float*)d_in[4];
    const float* w2 = (const float*)d_in[5];
    const float* b2 = (const float*)d_in[6];
    const float* w3 = (const float*)d_in[7];
    const float* b3 = (const float*)d_in[8];
    const float* w4 = (const float*)d_in[9];
    const float* b4 = (const float*)d_in[10];
    float* out = (float*)d_out;

    cudaFuncSetAttribute(k_gram,      cudaFuncAttributeMaxDynamicSharedMemorySize, DSMEM_GRAM);
    cudaFuncSetAttribute(k_ln,        cudaFuncAttributeMaxDynamicSharedMemorySize, LN_SMEM);
    cudaFuncSetAttribute(k_xm,        cudaFuncAttributeMaxDynamicSharedMemorySize, LN_SMEM);
    cudaFuncSetAttribute(k_gemm<0,1>, cudaFuncAttributeMaxDynamicSharedMemorySize, DSMEM_SZ);
    cudaFuncSetAttribute(k_gemm<1,1>, cudaFuncAttributeMaxDynamicSharedMemorySize, DSMEM_SZ);
    cudaFuncSetAttribute(k_gemm<2,1>, cudaFuncAttributeMaxDynamicSharedMemorySize, DSMEM_SZ);
    cudaFuncSetAttribute(k_gemm<0,2>, cudaFuncAttributeMaxDynamicSharedMemorySize, DSMEM_SZ);

    __half *wB, *cat, *m1p, *tp, *xlp;
    cudaGetSymbolAddress((void**)&wB,  g_wB);
    cudaGetSymbolAddress((void**)&cat, g_cat);
    cudaGetSymbolAddress((void**)&m1p, g_m1p);
    cudaGetSymbolAddress((void**)&tp,  g_tp);
    cudaGetSymbolAddress((void**)&xlp, g_xlp);

    k_avg1<<<dim3(8, NB), 192>>>(x);
    k_avg2<<<MTOT*DIMD/NTOK/256, 256>>>();
    k_ln  <<<MTOT/16, 256, LN_SMEM>>>(x, gamma, beta);
    k_gram<<<dim3(36, NB), 256, DSMEM_GRAM>>>();
    k_xm  <<<MTOT/16, 256, LN_SMEM>>>(x, w1);

    dim3 gg(DIMD/128, MTOT/128);
    // layer1: m1 = gelu(cat @ w1 + b1)            -> m1p (P16 only)
    k_gemm<0,1><<<gg,256,DSMEM_SZ>>>(cat, wB+W1B, b1, x, nullptr, m1p, nullptr, 2*DIMD);
    k_tr_rest<<<dim3(576, 3), 256>>>(w2, w3, w4);
    // layer2: t = x*m1*gelu(m1 @ w2 + b2)         -> tp (P16); m1 gating from m1p
    k_gemm<1,1><<<gg,256,DSMEM_SZ>>>(m1p, wB+W2B, b2, x, m1p,    tp,  nullptr, DIMD);
    // layer3: x*l3 = x*gelu(t @ w3 + b3)          -> xlp (P16)
    k_gemm<2,1><<<gg,256,DSMEM_SZ>>>(tp,  wB+W3B, b3, x, nullptr, xlp, nullptr, DIMD);
    // layer4: out = gelu((x*l3) @ w4 + b4)        -> out (row fp32)
    k_gemm<0,2><<<gg,256,DSMEM_SZ>>>(xlp, wB+W4B, b4, x, nullptr, nullptr, out, DIMD);
}